// round 5
// baseline (speedup 1.0000x reference)
#include <cuda_runtime.h>
#include <cuda_bf16.h>
#include <cstdint>

using bf16 = __nv_bfloat16;

// Problem constants
#define BSZ 4
#define LSEQ 2048
#define DDIM 512
#define EDIM 1024
#define NST 16
#define RRANK 32
#define NTOK (BSZ * LSEQ)          // 8192

// ---------------- scratch (device globals) ----------------
__device__ bf16  g_xzb[NTOK * 2 * EDIM];    // bf16 xz (conv + z source)
__device__ float g_dbl[NTOK * 64];          // fp32 (scan: B,C)
__device__ float g_dtT[NTOK * EDIM];        // [b][e][t] fp32
__device__ float g_xsT[NTOK * EDIM];        // [b][e][t] fp32
__device__ bf16  g_zT [NTOK * EDIM];        // [b][e][t] bf16
__device__ bf16  g_nrmb[NTOK * DDIM];       // GEMM A operands (bf16)
__device__ bf16  g_xsb [NTOK * EDIM];
__device__ bf16  g_dblb[NTOK * 64];
__device__ bf16  g_yb  [NTOK * EDIM];
__device__ bf16  g_winb [DDIM * 2 * EDIM];  // weights (bf16)
__device__ bf16  g_wxb  [EDIM * 64];
__device__ bf16  g_wdtb [RRANK * EDIM];
__device__ bf16  g_woutb[EDIM * DDIM];

// ---------------- PTX helpers ----------------
__device__ __forceinline__ uint32_t smem_u32(const void* p) {
    return (uint32_t)__cvta_generic_to_shared(p);
}
__device__ __forceinline__ void cp_async16(void* s, const void* g) {
    asm volatile("cp.async.cg.shared.global [%0], [%1], 16;\n"
                 :: "r"(smem_u32(s)), "l"(g));
}
__device__ __forceinline__ void cp_commit() { asm volatile("cp.async.commit_group;\n"); }
template <int N> __device__ __forceinline__ void cp_wait() {
    asm volatile("cp.async.wait_group %0;\n" :: "n"(N));
}
__device__ __forceinline__ void ldsm_x4(uint32_t& r0, uint32_t& r1, uint32_t& r2, uint32_t& r3,
                                        uint32_t a) {
    asm volatile("ldmatrix.sync.aligned.m8n8.x4.shared.b16 {%0,%1,%2,%3}, [%4];\n"
                 : "=r"(r0), "=r"(r1), "=r"(r2), "=r"(r3) : "r"(a));
}
__device__ __forceinline__ void ldsm_x4_t(uint32_t& r0, uint32_t& r1, uint32_t& r2, uint32_t& r3,
                                          uint32_t a) {
    asm volatile("ldmatrix.sync.aligned.m8n8.x4.trans.shared.b16 {%0,%1,%2,%3}, [%4];\n"
                 : "=r"(r0), "=r"(r1), "=r"(r2), "=r"(r3) : "r"(a));
}
__device__ __forceinline__ void mma_bf16(float& d0, float& d1, float& d2, float& d3,
                                         uint32_t a0, uint32_t a1, uint32_t a2, uint32_t a3,
                                         uint32_t b0, uint32_t b1) {
    asm volatile("mma.sync.aligned.m16n8k16.row.col.f32.bf16.bf16.f32 "
                 "{%0,%1,%2,%3}, {%4,%5,%6,%7}, {%8,%9}, {%0,%1,%2,%3};\n"
                 : "+f"(d0), "+f"(d1), "+f"(d2), "+f"(d3)
                 : "r"(a0), "r"(a1), "r"(a2), "r"(a3), "r"(b0), "r"(b1));
}
__device__ __forceinline__ float softplus_f(float v) {
    return (v > 20.0f) ? v : log1pf(expf(v));
}

// ---------------- fp32 -> bf16 convert ----------------
__global__ void f2bf_kernel(const float* __restrict__ in, bf16* __restrict__ out, int n) {
    int i = blockIdx.x * blockDim.x + threadIdx.x;
    if (i * 4 < n) {
        float4 v = *(const float4*)(in + i * 4);
        bf16 o[4] = {__float2bfloat16(v.x), __float2bfloat16(v.y),
                     __float2bfloat16(v.z), __float2bfloat16(v.w)};
        *(uint64_t*)(out + i * 4) = *(uint64_t*)o;
    }
}

// ---------------- RMSNorm -> bf16 ----------------
__global__ void rmsnorm_kernel(const float* __restrict__ x,
                               const float* __restrict__ w,
                               bf16* __restrict__ out) {
    int row = blockIdx.x;
    int tid = threadIdx.x;                // 128 threads x 4 floats
    float4 v = ((const float4*)(x + (size_t)row * DDIM))[tid];
    float ss = v.x * v.x + v.y * v.y + v.z * v.z + v.w * v.w;
    #pragma unroll
    for (int o = 16; o > 0; o >>= 1) ss += __shfl_xor_sync(0xffffffffu, ss, o);
    __shared__ float sred[4];
    if ((tid & 31) == 0) sred[tid >> 5] = ss;
    __syncthreads();
    float tot = sred[0] + sred[1] + sred[2] + sred[3];
    float scale = rsqrtf(tot * (1.0f / DDIM) + 1e-6f);
    float4 wv = ((const float4*)w)[tid];
    bf16 o[4] = {__float2bfloat16(v.x * scale * wv.x),
                 __float2bfloat16(v.y * scale * wv.y),
                 __float2bfloat16(v.z * scale * wv.z),
                 __float2bfloat16(v.w * scale * wv.w)};
    *(uint64_t*)(out + (size_t)row * DDIM + tid * 4) = *(uint64_t*)o;
}

// ---------------- bf16 tensor-core GEMM ----------------
// C(MxN) = A(MxK bf16, row-major) * B(KxN bf16, row-major)
// EPI: 0 fp32 | 2 fp32 + resid | 3 fp32 + bf16 C2 | 5 bf16 C2 only
template <int BM, int BN, int WGM, int WGN, int EPI>
__global__ void __launch_bounds__(WGM * WGN * 32)
gemm_bf16(const bf16* __restrict__ A, int lda,
          const bf16* __restrict__ B, int ldb,
          float* __restrict__ C, int ldc,
          int M, int N, int K,
          const float* __restrict__ resid,
          bf16* __restrict__ C2) {
    constexpr int BK = 32;
    constexpr int NTHR = WGM * WGN * 32;
    constexpr int WM = BM / WGM;
    constexpr int WN = BN / WGN;
    constexpr int MT = WM / 16;
    constexpr int NT = WN / 8;
    static_assert(NT % 2 == 0, "NT even");

    __shared__ __align__(16) bf16 As[2][BM][BK + 8];
    __shared__ __align__(16) bf16 Bs[2][BK][BN + 8];

    const int tid = threadIdx.x;
    const int warp = tid >> 5, lane = tid & 31;
    const int wm = (warp % WGM) * WM;
    const int wn = (warp / WGM) * WN;
    const int rowBase = blockIdx.y * BM;
    const int colBase = blockIdx.x * BN;

    float acc[MT][NT][4];
    #pragma unroll
    for (int i = 0; i < MT; i++)
        #pragma unroll
        for (int j = 0; j < NT; j++)
            #pragma unroll
            for (int q = 0; q < 4; q++) acc[i][j][q] = 0.0f;

    constexpr int A_CHUNKS = BM * BK / 8;
    constexpr int B_CHUNKS = BK * BN / 8;

    auto load_tile = [&](int buf, int k0) {
        #pragma unroll
        for (int c = tid; c < A_CHUNKS; c += NTHR) {
            int row = c / (BK / 8);
            int col = (c % (BK / 8)) * 8;
            cp_async16(&As[buf][row][col],
                       &A[(size_t)(rowBase + row) * lda + k0 + col]);
        }
        #pragma unroll
        for (int c = tid; c < B_CHUNKS; c += NTHR) {
            int row = c / (BN / 8);
            int col = (c % (BN / 8)) * 8;
            cp_async16(&Bs[buf][row][col],
                       &B[(size_t)(k0 + row) * ldb + colBase + col]);
        }
        cp_commit();
    };

    const int KT = K / BK;
    load_tile(0, 0);

    const int arow = lane & 15, acol = (lane >> 4) * 8;
    const int bq = lane >> 3, bl = lane & 7;
    const int bk = (bq & 1) * 8 + bl, bn = (bq >> 1) * 8;

    for (int kt = 0; kt < KT; kt++) {
        const int buf = kt & 1;
        if (kt + 1 < KT) {
            load_tile(buf ^ 1, (kt + 1) * BK);
            cp_wait<1>();
        } else {
            cp_wait<0>();
        }
        __syncthreads();

        #pragma unroll
        for (int ks = 0; ks < 2; ks++) {
            uint32_t a[MT][4];
            #pragma unroll
            for (int mt = 0; mt < MT; mt++)
                ldsm_x4(a[mt][0], a[mt][1], a[mt][2], a[mt][3],
                        smem_u32(&As[buf][wm + mt * 16 + arow][ks * 16 + acol]));
            uint32_t b[NT][2];
            #pragma unroll
            for (int nt2 = 0; nt2 < NT / 2; nt2++) {
                uint32_t r0, r1, r2, r3;
                ldsm_x4_t(r0, r1, r2, r3,
                          smem_u32(&Bs[buf][ks * 16 + bk][wn + nt2 * 16 + bn]));
                b[2 * nt2][0] = r0; b[2 * nt2][1] = r1;
                b[2 * nt2 + 1][0] = r2; b[2 * nt2 + 1][1] = r3;
            }
            #pragma unroll
            for (int mt = 0; mt < MT; mt++)
                #pragma unroll
                for (int nt = 0; nt < NT; nt++)
                    mma_bf16(acc[mt][nt][0], acc[mt][nt][1], acc[mt][nt][2], acc[mt][nt][3],
                             a[mt][0], a[mt][1], a[mt][2], a[mt][3],
                             b[nt][0], b[nt][1]);
        }
        __syncthreads();
    }

    // epilogue
    #pragma unroll
    for (int mt = 0; mt < MT; mt++) {
        #pragma unroll
        for (int nt = 0; nt < NT; nt++) {
            int col = colBase + wn + nt * 8 + (lane & 3) * 2;
            #pragma unroll
            for (int h = 0; h < 2; h++) {
                int row = rowBase + wm + mt * 16 + (lane >> 2) + h * 8;
                float v0 = acc[mt][nt][2 * h + 0];
                float v1 = acc[mt][nt][2 * h + 1];
                if (EPI == 2) {
                    const float2 r = *(const float2*)&resid[(size_t)row * ldc + col];
                    v0 += r.x; v1 += r.y;
                }
                if constexpr (EPI != 5) {
                    *(float2*)&C[(size_t)row * ldc + col] = make_float2(v0, v1);
                }
                if (EPI == 3 || EPI == 5) {
                    bf16 o[2] = {__float2bfloat16(v0), __float2bfloat16(v1)};
                    *(uint32_t*)&C2[(size_t)row * ldc + col] = *(uint32_t*)o;
                }
            }
        }
    }
}

// ---------------- dedicated dt GEMM: dtT = softplus(dbl[:, :32] @ W_dt + b_dt), transposed out ----
__global__ void __launch_bounds__(256)
dtgemm_kernel(const bf16* __restrict__ A,      // dblb, lda=64 (use cols 0..31)
              const bf16* __restrict__ B,      // wdtb, 32 x 1024
              const float* __restrict__ bias,
              float* __restrict__ dtT) {
    __shared__ __align__(16) bf16 As[128][40];
    __shared__ __align__(16) bf16 Bs[32][136];
    __shared__ float sbuf[32][129];

    const int tid = threadIdx.x, warp = tid >> 5, lane = tid & 31;
    const int wm = (warp & 1) * 64;
    const int wn = (warp >> 1) * 32;
    const int rowBase = blockIdx.y * 128;
    const int colBase = blockIdx.x * 128;

    #pragma unroll
    for (int c = tid; c < 512; c += 256) {
        int r = c >> 2, q = (c & 3) * 8;
        cp_async16(&As[r][q], &A[(size_t)(rowBase + r) * 64 + q]);
    }
    #pragma unroll
    for (int c = tid; c < 512; c += 256) {
        int r = c >> 4, q = (c & 15) * 8;
        cp_async16(&Bs[r][q], &B[(size_t)r * EDIM + colBase + q]);
    }
    cp_commit(); cp_wait<0>(); __syncthreads();

    float acc[4][4][4];
    #pragma unroll
    for (int i = 0; i < 4; i++)
        #pragma unroll
        for (int j = 0; j < 4; j++)
            #pragma unroll
            for (int q = 0; q < 4; q++) acc[i][j][q] = 0.0f;

    const int arow = lane & 15, acol = (lane >> 4) * 8;
    const int bq = lane >> 3, bl = lane & 7;
    const int bk = (bq & 1) * 8 + bl, bn = (bq >> 1) * 8;

    #pragma unroll
    for (int ks = 0; ks < 2; ks++) {
        uint32_t a[4][4];
        #pragma unroll
        for (int mt = 0; mt < 4; mt++)
            ldsm_x4(a[mt][0], a[mt][1], a[mt][2], a[mt][3],
                    smem_u32(&As[wm + mt * 16 + arow][ks * 16 + acol]));
        uint32_t b[4][2];
        #pragma unroll
        for (int nt2 = 0; nt2 < 2; nt2++) {
            uint32_t r0, r1, r2, r3;
            ldsm_x4_t(r0, r1, r2, r3,
                      smem_u32(&Bs[ks * 16 + bk][wn + nt2 * 16 + bn]));
            b[2 * nt2][0] = r0; b[2 * nt2][1] = r1;
            b[2 * nt2 + 1][0] = r2; b[2 * nt2 + 1][1] = r3;
        }
        #pragma unroll
        for (int mt = 0; mt < 4; mt++)
            #pragma unroll
            for (int nt = 0; nt < 4; nt++)
                mma_bf16(acc[mt][nt][0], acc[mt][nt][1], acc[mt][nt][2], acc[mt][nt][3],
                         a[mt][0], a[mt][1], a[mt][2], a[mt][3],
                         b[nt][0], b[nt][1]);
    }

    // transposed epilogue: 4 chunks of 32 columns
    const int bb = rowBase >> 11;        // / LSEQ
    const int tb = rowBase & 2047;
    #pragma unroll
    for (int cc = 0; cc < 4; cc++) {
        __syncthreads();
        if (wn == cc * 32) {
            #pragma unroll
            for (int mt = 0; mt < 4; mt++)
                #pragma unroll
                for (int nt = 0; nt < 4; nt++) {
                    int c = nt * 8 + (lane & 3) * 2;
                    int col = colBase + wn + c;
                    #pragma unroll
                    for (int h = 0; h < 2; h++) {
                        int r = wm + mt * 16 + (lane >> 2) + h * 8;
                        sbuf[c][r]     = softplus_f(acc[mt][nt][2 * h]     + bias[col]);
                        sbuf[c + 1][r] = softplus_f(acc[mt][nt][2 * h + 1] + bias[col + 1]);
                    }
                }
        }
        __syncthreads();
        for (int j = tid; j < 32 * 128; j += 256) {
            int c = j >> 7, r = j & 127;
            dtT[((size_t)bb * EDIM + colBase + cc * 32 + c) * LSEQ + tb + r] = sbuf[c][r];
        }
    }
}

// ---------------- fused conv+silu+transposes ----------------
// reads bf16 xz; writes xsb (bf16 [t][e]), xsT (fp32 [e][t]), zT (bf16 [e][t])
__global__ void __launch_bounds__(256)
conv_fused_kernel(const bf16* __restrict__ xzb,
                  const float* __restrict__ conv_w,
                  const float* __restrict__ conv_b,
                  bf16* __restrict__ xsb,
                  float* __restrict__ xsT,
                  bf16* __restrict__ zT) {
    __shared__ float xt[35][65];
    __shared__ float st[32][65];
    __shared__ bf16  zt[32][66];

    const int e0 = blockIdx.x * 64;
    const int t0 = blockIdx.y * 32;
    const int b  = blockIdx.z;
    const int tx = threadIdx.x & 31, ty = threadIdx.x >> 5;   // 32 x 8

    for (int i = ty; i < 35; i += 8) {
        int t = t0 - 3 + i;
        uint32_t pv = 0;
        if (t >= 0)
            pv = *(const uint32_t*)&xzb[((size_t)(b * LSEQ + t)) * (2 * EDIM) + e0 + 2 * tx];
        bf16 p[2]; *(uint32_t*)p = pv;
        xt[i][2 * tx]     = __bfloat162float(p[0]);
        xt[i][2 * tx + 1] = __bfloat162float(p[1]);
    }
    for (int i = ty; i < 32; i += 8) {
        uint32_t pv = *(const uint32_t*)&xzb[((size_t)(b * LSEQ + t0 + i)) * (2 * EDIM) + EDIM + e0 + 2 * tx];
        *(uint32_t*)&zt[i][2 * tx] = pv;
    }
    __syncthreads();

    const int ea = e0 + 2 * tx, ebx = ea + 1;
    const float w0a = conv_w[ea * 4 + 0], w1a = conv_w[ea * 4 + 1],
                w2a = conv_w[ea * 4 + 2], w3a = conv_w[ea * 4 + 3], bba = conv_b[ea];
    const float w0b = conv_w[ebx * 4 + 0], w1b = conv_w[ebx * 4 + 1],
                w2b = conv_w[ebx * 4 + 2], w3b = conv_w[ebx * 4 + 3], bbb = conv_b[ebx];

    for (int i = ty; i < 32; i += 8) {
        float a0 = bba + w0a * xt[i][2*tx] + w1a * xt[i+1][2*tx]
                       + w2a * xt[i+2][2*tx] + w3a * xt[i+3][2*tx];
        float a1 = bbb + w0b * xt[i][2*tx+1] + w1b * xt[i+1][2*tx+1]
                       + w2b * xt[i+2][2*tx+1] + w3b * xt[i+3][2*tx+1];
        float s0 = a0 / (1.0f + __expf(-a0));
        float s1 = a1 / (1.0f + __expf(-a1));
        st[i][2*tx] = s0; st[i][2*tx+1] = s1;
        bf16 o[2] = {__float2bfloat16(s0), __float2bfloat16(s1)};
        *(uint32_t*)&xsb[((size_t)(b * LSEQ + t0 + i)) * EDIM + e0 + 2 * tx] = *(uint32_t*)o;
    }
    __syncthreads();

    for (int i = ty; i < 64; i += 8) {
        xsT[((size_t)b * EDIM + e0 + i) * LSEQ + t0 + tx] = st[tx][i];
        zT [((size_t)b * EDIM + e0 + i) * LSEQ + t0 + tx] = zt[tx][i];
    }
}

// ---------------- chunked parallel selective scan ----------------
#define CHUNK 64
__global__ void __launch_bounds__(256)
scan_kernel(const float* __restrict__ dtT,
            const float* __restrict__ xsT,
            const bf16*  __restrict__ zT,
            const float* __restrict__ dbl,
            const float* __restrict__ A_log,
            const float* __restrict__ D_skip,
            bf16* __restrict__ y) {
    const int b    = blockIdx.y;
    const int warp = threadIdx.x >> 5;
    const int lane = threadIdx.x & 31;
    const int e    = blockIdx.x * 8 + warp;

    __shared__ bf16 ystage[8][LSEQ + 32];

    float Acoef[NST];
    #pragma unroll
    for (int n = 0; n < NST; n++) Acoef[n] = -__expf(A_log[e * NST + n]);
    const float dsk = D_skip[e];

    const float* dtp  = dtT + ((size_t)b * EDIM + e) * LSEQ;
    const float* xsp  = xsT + ((size_t)b * EDIM + e) * LSEQ;
    const bf16*  zp   = zT  + ((size_t)b * EDIM + e) * LSEQ;
    const float* dblp = dbl + (size_t)b * LSEQ * 64;

    const int t0 = lane * CHUNK;

    float P[NST], q[NST];
    #pragma unroll
    for (int n = 0; n < NST; n++) { P[n] = 1.0f; q[n] = 0.0f; }

    for (int s = 0; s < CHUNK; s++) {
        const int t = t0 + s;
        const float dtv = dtp[t];
        const float xsv = xsp[t];
        float Bv[NST];
        #pragma unroll
        for (int j = 0; j < 4; j++) {
            float4 tb = *(const float4*)&dblp[(size_t)t * 64 + RRANK + j * 4];
            Bv[j*4+0] = tb.x; Bv[j*4+1] = tb.y; Bv[j*4+2] = tb.z; Bv[j*4+3] = tb.w;
        }
        const float dx = dtv * xsv;
        #pragma unroll
        for (int n = 0; n < NST; n++) {
            float dA = __expf(dtv * Acoef[n]);
            q[n] = fmaf(dA, q[n], dx * Bv[n]);
            P[n] *= dA;
        }
    }

    #pragma unroll
    for (int d = 1; d < 32; d <<= 1) {
        #pragma unroll
        for (int n = 0; n < NST; n++) {
            float Pp = __shfl_up_sync(0xffffffffu, P[n], d);
            float qp = __shfl_up_sync(0xffffffffu, q[n], d);
            if (lane >= d) {
                q[n] = fmaf(P[n], qp, q[n]);
                P[n] *= Pp;
            }
        }
    }
    float h[NST];
    #pragma unroll
    for (int n = 0; n < NST; n++) {
        float v = __shfl_up_sync(0xffffffffu, q[n], 1);
        h[n] = (lane == 0) ? 0.0f : v;
    }

    for (int s = 0; s < CHUNK; s++) {
        const int t = t0 + s;
        const float dtv = dtp[t];
        const float xsv = xsp[t];
        float Bv[NST], Cv[NST];
        #pragma unroll
        for (int j = 0; j < 4; j++) {
            float4 tb = *(const float4*)&dblp[(size_t)t * 64 + RRANK + j * 4];
            float4 tc = *(const float4*)&dblp[(size_t)t * 64 + RRANK + NST + j * 4];
            Bv[j*4+0] = tb.x; Bv[j*4+1] = tb.y; Bv[j*4+2] = tb.z; Bv[j*4+3] = tb.w;
            Cv[j*4+0] = tc.x; Cv[j*4+1] = tc.y; Cv[j*4+2] = tc.z; Cv[j*4+3] = tc.w;
        }
        const float dx = dtv * xsv;
        float yacc0 = 0.0f, yacc1 = 0.0f;
        #pragma unroll
        for (int n = 0; n < NST; n += 2) {
            float dA0 = __expf(dtv * Acoef[n]);
            float dA1 = __expf(dtv * Acoef[n + 1]);
            h[n]     = fmaf(dA0, h[n],     dx * Bv[n]);
            h[n + 1] = fmaf(dA1, h[n + 1], dx * Bv[n + 1]);
            yacc0 = fmaf(h[n],     Cv[n],     yacc0);
            yacc1 = fmaf(h[n + 1], Cv[n + 1], yacc1);
        }
        const float zv  = __bfloat162float(zp[t]);
        const float sig = 1.0f / (1.0f + __expf(-zv));
        const float out = ((yacc0 + yacc1) + xsv * dsk) * (zv * sig);
        ystage[warp][t + (t >> 6)] = __float2bfloat16(out);
    }
    __syncthreads();

    const int e0 = blockIdx.x * 8;
    for (int t = threadIdx.x; t < LSEQ; t += 256) {
        bf16 v[8];
        #pragma unroll
        for (int w = 0; w < 8; w++) v[w] = ystage[w][t + (t >> 6)];
        *(uint4*)&y[((size_t)(b * LSEQ + t)) * EDIM + e0] = *(uint4*)v;
    }
}

// ---------------- launcher ----------------
extern "C" void kernel_launch(void* const* d_in, const int* in_sizes, int n_in,
                              void* d_out, int out_size) {
    const float* hidden = (const float*)d_in[0];
    const float* norm_w = (const float*)d_in[1];
    const float* W_in   = (const float*)d_in[2];
    const float* conv_w = (const float*)d_in[3];
    const float* conv_b = (const float*)d_in[4];
    const float* W_x    = (const float*)d_in[5];
    const float* W_dt   = (const float*)d_in[6];
    const float* b_dt   = (const float*)d_in[7];
    const float* A_log  = (const float*)d_in[8];
    const float* D_skip = (const float*)d_in[9];
    const float* W_out  = (const float*)d_in[10];
    float* out = (float*)d_out;

    float *p_dbl, *p_dtT, *p_xsT;
    bf16 *p_xzb, *p_zT, *p_nrmb, *p_xsb, *p_dblb, *p_yb;
    bf16 *p_winb, *p_wxb, *p_wdtb, *p_woutb;
    cudaGetSymbolAddress((void**)&p_xzb,  g_xzb);
    cudaGetSymbolAddress((void**)&p_dbl,  g_dbl);
    cudaGetSymbolAddress((void**)&p_dtT,  g_dtT);
    cudaGetSymbolAddress((void**)&p_xsT,  g_xsT);
    cudaGetSymbolAddress((void**)&p_zT,   g_zT);
    cudaGetSymbolAddress((void**)&p_nrmb, g_nrmb);
    cudaGetSymbolAddress((void**)&p_xsb,  g_xsb);
    cudaGetSymbolAddress((void**)&p_dblb, g_dblb);
    cudaGetSymbolAddress((void**)&p_yb,   g_yb);
    cudaGetSymbolAddress((void**)&p_winb, g_winb);
    cudaGetSymbolAddress((void**)&p_wxb,  g_wxb);
    cudaGetSymbolAddress((void**)&p_wdtb, g_wdtb);
    cudaGetSymbolAddress((void**)&p_woutb, g_woutb);

    // 0) weight conversion to bf16
    f2bf_kernel<<<(DDIM * 2 * EDIM / 4 + 255) / 256, 256>>>(W_in,  p_winb,  DDIM * 2 * EDIM);
    f2bf_kernel<<<(EDIM * 64 / 4 + 255) / 256, 256>>>(W_x,   p_wxb,   EDIM * 64);
    f2bf_kernel<<<(RRANK * EDIM / 4 + 255) / 256, 256>>>(W_dt, p_wdtb, RRANK * EDIM);
    f2bf_kernel<<<(EDIM * DDIM / 4 + 255) / 256, 256>>>(W_out, p_woutb, EDIM * DDIM);

    // 1) RMSNorm -> bf16
    rmsnorm_kernel<<<NTOK, 128>>>(hidden, norm_w, p_nrmb);

    // 2) xz = nrm @ W_in -> bf16 only
    gemm_bf16<128, 128, 2, 4, 5><<<dim3(2 * EDIM / 128, NTOK / 128), 256>>>(
        p_nrmb, DDIM, p_winb, 2 * EDIM, nullptr, 2 * EDIM,
        NTOK, 2 * EDIM, DDIM, nullptr, p_xzb);

    // 3) fused conv + silu + transposes
    conv_fused_kernel<<<dim3(EDIM / 64, LSEQ / 32, BSZ), 256>>>(
        p_xzb, conv_w, conv_b, p_xsb, p_xsT, p_zT);

    // 4) dbl = xs @ W_x -> fp32 + bf16
    gemm_bf16<64, 64, 4, 2, 3><<<dim3(1, NTOK / 64), 256>>>(
        p_xsb, EDIM, p_wxb, 64, p_dbl, 64,
        NTOK, 64, EDIM, nullptr, p_dblb);

    // 5) dtT = softplus(dbl[:, :32] @ W_dt + b_dt), transposed write
    dtgemm_kernel<<<dim3(EDIM / 128, NTOK / 128), 256>>>(p_dblb, p_wdtb, b_dt, p_dtT);

    // 6) chunked parallel scan + gate -> bf16 y
    scan_kernel<<<dim3(EDIM / 8, BSZ), 256>>>(p_dtT, p_xsT, p_zT, p_dbl, A_log, D_skip, p_yb);

    // 7) out = y @ W_out + hidden -> fp32
    gemm_bf16<128, 128, 2, 4, 2><<<dim3(DDIM / 128, NTOK / 128), 256>>>(
        p_yb, EDIM, p_woutb, DDIM, out, DDIM,
        NTOK, DDIM, EDIM, hidden, nullptr);
}

// round 6
// speedup vs baseline: 1.9596x; 1.9596x over previous
#include <cuda_runtime.h>
#include <cuda_bf16.h>
#include <cstdint>

using bf16 = __nv_bfloat16;

// Problem constants
#define BSZ 4
#define LSEQ 2048
#define DDIM 512
#define EDIM 1024
#define NST 16
#define RRANK 32
#define NTOK (BSZ * LSEQ)          // 8192

// ---------------- scratch (device globals) ----------------
__device__ bf16  g_xzb[NTOK * 2 * EDIM];    // bf16 xz (conv + z source)
__device__ float g_dtT[NTOK * EDIM];        // [b][e][t] fp32
__device__ float g_xsT[NTOK * EDIM];        // [b][e][t] fp32
__device__ bf16  g_zT [NTOK * EDIM];        // [b][e][t] bf16
__device__ bf16  g_nrmb[NTOK * DDIM];       // GEMM A operands (bf16)
__device__ bf16  g_xsb [NTOK * EDIM];
__device__ bf16  g_dblb[NTOK * 64];         // full dbl bf16 (dt gemm input)
__device__ bf16  g_bcb [NTOK * 32];         // compact B,C bf16 (scan input)
__device__ bf16  g_yb  [NTOK * EDIM];
__device__ bf16  g_winb [DDIM * 2 * EDIM];  // weights (bf16)
__device__ bf16  g_wxb  [EDIM * 64];
__device__ bf16  g_wdtb [RRANK * EDIM];
__device__ bf16  g_woutb[EDIM * DDIM];

// ---------------- PTX helpers ----------------
__device__ __forceinline__ uint32_t smem_u32(const void* p) {
    return (uint32_t)__cvta_generic_to_shared(p);
}
__device__ __forceinline__ void cp_async16(void* s, const void* g) {
    asm volatile("cp.async.cg.shared.global [%0], [%1], 16;\n"
                 :: "r"(smem_u32(s)), "l"(g));
}
__device__ __forceinline__ void cp_commit() { asm volatile("cp.async.commit_group;\n"); }
template <int N> __device__ __forceinline__ void cp_wait() {
    asm volatile("cp.async.wait_group %0;\n" :: "n"(N));
}
__device__ __forceinline__ void ldsm_x4(uint32_t& r0, uint32_t& r1, uint32_t& r2, uint32_t& r3,
                                        uint32_t a) {
    asm volatile("ldmatrix.sync.aligned.m8n8.x4.shared.b16 {%0,%1,%2,%3}, [%4];\n"
                 : "=r"(r0), "=r"(r1), "=r"(r2), "=r"(r3) : "r"(a));
}
__device__ __forceinline__ void ldsm_x4_t(uint32_t& r0, uint32_t& r1, uint32_t& r2, uint32_t& r3,
                                          uint32_t a) {
    asm volatile("ldmatrix.sync.aligned.m8n8.x4.trans.shared.b16 {%0,%1,%2,%3}, [%4];\n"
                 : "=r"(r0), "=r"(r1), "=r"(r2), "=r"(r3) : "r"(a));
}
__device__ __forceinline__ void mma_bf16(float& d0, float& d1, float& d2, float& d3,
                                         uint32_t a0, uint32_t a1, uint32_t a2, uint32_t a3,
                                         uint32_t b0, uint32_t b1) {
    asm volatile("mma.sync.aligned.m16n8k16.row.col.f32.bf16.bf16.f32 "
                 "{%0,%1,%2,%3}, {%4,%5,%6,%7}, {%8,%9}, {%0,%1,%2,%3};\n"
                 : "+f"(d0), "+f"(d1), "+f"(d2), "+f"(d3)
                 : "r"(a0), "r"(a1), "r"(a2), "r"(a3), "r"(b0), "r"(b1));
}
__device__ __forceinline__ float softplus_f(float v) {
    return (v > 20.0f) ? v : log1pf(expf(v));
}
// unpack 8 bf16 (uint4) -> 8 floats
__device__ __forceinline__ void unpack8(uint4 v, float* f) {
    uint32_t u[4] = {v.x, v.y, v.z, v.w};
    #pragma unroll
    for (int j = 0; j < 4; j++) {
        f[2 * j]     = __uint_as_float(u[j] << 16);
        f[2 * j + 1] = __uint_as_float(u[j] & 0xffff0000u);
    }
}

// ---------------- fp32 -> bf16 convert ----------------
__global__ void f2bf_kernel(const float* __restrict__ in, bf16* __restrict__ out, int n) {
    int i = blockIdx.x * blockDim.x + threadIdx.x;
    if (i * 4 < n) {
        float4 v = *(const float4*)(in + i * 4);
        bf16 o[4] = {__float2bfloat16(v.x), __float2bfloat16(v.y),
                     __float2bfloat16(v.z), __float2bfloat16(v.w)};
        *(uint64_t*)(out + i * 4) = *(uint64_t*)o;
    }
}

// ---------------- RMSNorm -> bf16 ----------------
__global__ void rmsnorm_kernel(const float* __restrict__ x,
                               const float* __restrict__ w,
                               bf16* __restrict__ out) {
    int row = blockIdx.x;
    int tid = threadIdx.x;                // 128 threads x 4 floats
    float4 v = ((const float4*)(x + (size_t)row * DDIM))[tid];
    float ss = v.x * v.x + v.y * v.y + v.z * v.z + v.w * v.w;
    #pragma unroll
    for (int o = 16; o > 0; o >>= 1) ss += __shfl_xor_sync(0xffffffffu, ss, o);
    __shared__ float sred[4];
    if ((tid & 31) == 0) sred[tid >> 5] = ss;
    __syncthreads();
    float tot = sred[0] + sred[1] + sred[2] + sred[3];
    float scale = rsqrtf(tot * (1.0f / DDIM) + 1e-6f);
    float4 wv = ((const float4*)w)[tid];
    bf16 o[4] = {__float2bfloat16(v.x * scale * wv.x),
                 __float2bfloat16(v.y * scale * wv.y),
                 __float2bfloat16(v.z * scale * wv.z),
                 __float2bfloat16(v.w * scale * wv.w)};
    *(uint64_t*)(out + (size_t)row * DDIM + tid * 4) = *(uint64_t*)o;
}

// ---------------- bf16 tensor-core GEMM ----------------
// C(MxN) = A(MxK bf16, row-major) * B(KxN bf16, row-major)
// EPI: 2 fp32 + resid | 5 bf16 C2 only | 6 bf16 C2 + compact bf16 C3 (cols>=32)
template <int BM, int BN, int WGM, int WGN, int EPI>
__global__ void __launch_bounds__(WGM * WGN * 32)
gemm_bf16(const bf16* __restrict__ A, int lda,
          const bf16* __restrict__ B, int ldb,
          float* __restrict__ C, int ldc,
          int M, int N, int K,
          const float* __restrict__ resid,
          bf16* __restrict__ C2,
          bf16* __restrict__ C3) {
    constexpr int BK = 32;
    constexpr int NTHR = WGM * WGN * 32;
    constexpr int WM = BM / WGM;
    constexpr int WN = BN / WGN;
    constexpr int MT = WM / 16;
    constexpr int NT = WN / 8;
    static_assert(NT % 2 == 0, "NT even");

    __shared__ __align__(16) bf16 As[2][BM][BK + 8];
    __shared__ __align__(16) bf16 Bs[2][BK][BN + 8];

    const int tid = threadIdx.x;
    const int warp = tid >> 5, lane = tid & 31;
    const int wm = (warp % WGM) * WM;
    const int wn = (warp / WGM) * WN;
    const int rowBase = blockIdx.y * BM;
    const int colBase = blockIdx.x * BN;

    float acc[MT][NT][4];
    #pragma unroll
    for (int i = 0; i < MT; i++)
        #pragma unroll
        for (int j = 0; j < NT; j++)
            #pragma unroll
            for (int q = 0; q < 4; q++) acc[i][j][q] = 0.0f;

    constexpr int A_CHUNKS = BM * BK / 8;
    constexpr int B_CHUNKS = BK * BN / 8;

    auto load_tile = [&](int buf, int k0) {
        #pragma unroll
        for (int c = tid; c < A_CHUNKS; c += NTHR) {
            int row = c / (BK / 8);
            int col = (c % (BK / 8)) * 8;
            cp_async16(&As[buf][row][col],
                       &A[(size_t)(rowBase + row) * lda + k0 + col]);
        }
        #pragma unroll
        for (int c = tid; c < B_CHUNKS; c += NTHR) {
            int row = c / (BN / 8);
            int col = (c % (BN / 8)) * 8;
            cp_async16(&Bs[buf][row][col],
                       &B[(size_t)(k0 + row) * ldb + colBase + col]);
        }
        cp_commit();
    };

    const int KT = K / BK;
    load_tile(0, 0);

    const int arow = lane & 15, acol = (lane >> 4) * 8;
    const int bq = lane >> 3, bl = lane & 7;
    const int bk = (bq & 1) * 8 + bl, bn = (bq >> 1) * 8;

    for (int kt = 0; kt < KT; kt++) {
        const int buf = kt & 1;
        if (kt + 1 < KT) {
            load_tile(buf ^ 1, (kt + 1) * BK);
            cp_wait<1>();
        } else {
            cp_wait<0>();
        }
        __syncthreads();

        #pragma unroll
        for (int ks = 0; ks < 2; ks++) {
            uint32_t a[MT][4];
            #pragma unroll
            for (int mt = 0; mt < MT; mt++)
                ldsm_x4(a[mt][0], a[mt][1], a[mt][2], a[mt][3],
                        smem_u32(&As[buf][wm + mt * 16 + arow][ks * 16 + acol]));
            uint32_t b[NT][2];
            #pragma unroll
            for (int nt2 = 0; nt2 < NT / 2; nt2++) {
                uint32_t r0, r1, r2, r3;
                ldsm_x4_t(r0, r1, r2, r3,
                          smem_u32(&Bs[buf][ks * 16 + bk][wn + nt2 * 16 + bn]));
                b[2 * nt2][0] = r0; b[2 * nt2][1] = r1;
                b[2 * nt2 + 1][0] = r2; b[2 * nt2 + 1][1] = r3;
            }
            #pragma unroll
            for (int mt = 0; mt < MT; mt++)
                #pragma unroll
                for (int nt = 0; nt < NT; nt++)
                    mma_bf16(acc[mt][nt][0], acc[mt][nt][1], acc[mt][nt][2], acc[mt][nt][3],
                             a[mt][0], a[mt][1], a[mt][2], a[mt][3],
                             b[nt][0], b[nt][1]);
        }
        __syncthreads();
    }

    // epilogue
    #pragma unroll
    for (int mt = 0; mt < MT; mt++) {
        #pragma unroll
        for (int nt = 0; nt < NT; nt++) {
            int col = colBase + wn + nt * 8 + (lane & 3) * 2;
            #pragma unroll
            for (int h = 0; h < 2; h++) {
                int row = rowBase + wm + mt * 16 + (lane >> 2) + h * 8;
                float v0 = acc[mt][nt][2 * h + 0];
                float v1 = acc[mt][nt][2 * h + 1];
                if (EPI == 2) {
                    const float2 r = *(const float2*)&resid[(size_t)row * ldc + col];
                    v0 += r.x; v1 += r.y;
                    *(float2*)&C[(size_t)row * ldc + col] = make_float2(v0, v1);
                }
                if (EPI == 5 || EPI == 6) {
                    bf16 o[2] = {__float2bfloat16(v0), __float2bfloat16(v1)};
                    *(uint32_t*)&C2[(size_t)row * ldc + col] = *(uint32_t*)o;
                    if (EPI == 6 && col >= RRANK)
                        *(uint32_t*)&C3[(size_t)row * 32 + col - RRANK] = *(uint32_t*)o;
                }
            }
        }
    }
}

// ---------------- dedicated dt GEMM: dtT = softplus(dbl[:, :32] @ W_dt + b_dt), transposed out ----
__global__ void __launch_bounds__(256)
dtgemm_kernel(const bf16* __restrict__ A,      // dblb, lda=64 (use cols 0..31)
              const bf16* __restrict__ B,      // wdtb, 32 x 1024
              const float* __restrict__ bias,
              float* __restrict__ dtT) {
    __shared__ __align__(16) bf16 As[128][40];
    __shared__ __align__(16) bf16 Bs[32][136];
    __shared__ float sbuf[32][129];

    const int tid = threadIdx.x, warp = tid >> 5, lane = tid & 31;
    const int wm = (warp & 1) * 64;
    const int wn = (warp >> 1) * 32;
    const int rowBase = blockIdx.y * 128;
    const int colBase = blockIdx.x * 128;

    #pragma unroll
    for (int c = tid; c < 512; c += 256) {
        int r = c >> 2, q = (c & 3) * 8;
        cp_async16(&As[r][q], &A[(size_t)(rowBase + r) * 64 + q]);
    }
    #pragma unroll
    for (int c = tid; c < 512; c += 256) {
        int r = c >> 4, q = (c & 15) * 8;
        cp_async16(&Bs[r][q], &B[(size_t)r * EDIM + colBase + q]);
    }
    cp_commit(); cp_wait<0>(); __syncthreads();

    float acc[4][4][4];
    #pragma unroll
    for (int i = 0; i < 4; i++)
        #pragma unroll
        for (int j = 0; j < 4; j++)
            #pragma unroll
            for (int q = 0; q < 4; q++) acc[i][j][q] = 0.0f;

    const int arow = lane & 15, acol = (lane >> 4) * 8;
    const int bq = lane >> 3, bl = lane & 7;
    const int bk = (bq & 1) * 8 + bl, bn = (bq >> 1) * 8;

    #pragma unroll
    for (int ks = 0; ks < 2; ks++) {
        uint32_t a[4][4];
        #pragma unroll
        for (int mt = 0; mt < 4; mt++)
            ldsm_x4(a[mt][0], a[mt][1], a[mt][2], a[mt][3],
                    smem_u32(&As[wm + mt * 16 + arow][ks * 16 + acol]));
        uint32_t b[4][2];
        #pragma unroll
        for (int nt2 = 0; nt2 < 2; nt2++) {
            uint32_t r0, r1, r2, r3;
            ldsm_x4_t(r0, r1, r2, r3,
                      smem_u32(&Bs[ks * 16 + bk][wn + nt2 * 16 + bn]));
            b[2 * nt2][0] = r0; b[2 * nt2][1] = r1;
            b[2 * nt2 + 1][0] = r2; b[2 * nt2 + 1][1] = r3;
        }
        #pragma unroll
        for (int mt = 0; mt < 4; mt++)
            #pragma unroll
            for (int nt = 0; nt < 4; nt++)
                mma_bf16(acc[mt][nt][0], acc[mt][nt][1], acc[mt][nt][2], acc[mt][nt][3],
                         a[mt][0], a[mt][1], a[mt][2], a[mt][3],
                         b[nt][0], b[nt][1]);
    }

    // transposed epilogue: 4 chunks of 32 columns
    const int bb = rowBase >> 11;        // / LSEQ
    const int tb = rowBase & 2047;
    #pragma unroll
    for (int cc = 0; cc < 4; cc++) {
        __syncthreads();
        if (wn == cc * 32) {
            #pragma unroll
            for (int mt = 0; mt < 4; mt++)
                #pragma unroll
                for (int nt = 0; nt < 4; nt++) {
                    int c = nt * 8 + (lane & 3) * 2;
                    int col = colBase + wn + c;
                    #pragma unroll
                    for (int h = 0; h < 2; h++) {
                        int r = wm + mt * 16 + (lane >> 2) + h * 8;
                        sbuf[c][r]     = softplus_f(acc[mt][nt][2 * h]     + bias[col]);
                        sbuf[c + 1][r] = softplus_f(acc[mt][nt][2 * h + 1] + bias[col + 1]);
                    }
                }
        }
        __syncthreads();
        for (int j = tid; j < 32 * 128; j += 256) {
            int c = j >> 7, r = j & 127;
            dtT[((size_t)bb * EDIM + colBase + cc * 32 + c) * LSEQ + tb + r] = sbuf[c][r];
        }
    }
}

// ---------------- fused conv+silu+transposes ----------------
__global__ void __launch_bounds__(256)
conv_fused_kernel(const bf16* __restrict__ xzb,
                  const float* __restrict__ conv_w,
                  const float* __restrict__ conv_b,
                  bf16* __restrict__ xsb,
                  float* __restrict__ xsT,
                  bf16* __restrict__ zT) {
    __shared__ float xt[35][65];
    __shared__ float st[32][65];
    __shared__ bf16  zt[32][66];

    const int e0 = blockIdx.x * 64;
    const int t0 = blockIdx.y * 32;
    const int b  = blockIdx.z;
    const int tx = threadIdx.x & 31, ty = threadIdx.x >> 5;   // 32 x 8

    for (int i = ty; i < 35; i += 8) {
        int t = t0 - 3 + i;
        uint32_t pv = 0;
        if (t >= 0)
            pv = *(const uint32_t*)&xzb[((size_t)(b * LSEQ + t)) * (2 * EDIM) + e0 + 2 * tx];
        bf16 p[2]; *(uint32_t*)p = pv;
        xt[i][2 * tx]     = __bfloat162float(p[0]);
        xt[i][2 * tx + 1] = __bfloat162float(p[1]);
    }
    for (int i = ty; i < 32; i += 8) {
        uint32_t pv = *(const uint32_t*)&xzb[((size_t)(b * LSEQ + t0 + i)) * (2 * EDIM) + EDIM + e0 + 2 * tx];
        *(uint32_t*)&zt[i][2 * tx] = pv;
    }
    __syncthreads();

    const int ea = e0 + 2 * tx, ebx = ea + 1;
    const float w0a = conv_w[ea * 4 + 0], w1a = conv_w[ea * 4 + 1],
                w2a = conv_w[ea * 4 + 2], w3a = conv_w[ea * 4 + 3], bba = conv_b[ea];
    const float w0b = conv_w[ebx * 4 + 0], w1b = conv_w[ebx * 4 + 1],
                w2b = conv_w[ebx * 4 + 2], w3b = conv_w[ebx * 4 + 3], bbb = conv_b[ebx];

    for (int i = ty; i < 32; i += 8) {
        float a0 = bba + w0a * xt[i][2*tx] + w1a * xt[i+1][2*tx]
                       + w2a * xt[i+2][2*tx] + w3a * xt[i+3][2*tx];
        float a1 = bbb + w0b * xt[i][2*tx+1] + w1b * xt[i+1][2*tx+1]
                       + w2b * xt[i+2][2*tx+1] + w3b * xt[i+3][2*tx+1];
        float s0 = a0 / (1.0f + __expf(-a0));
        float s1 = a1 / (1.0f + __expf(-a1));
        st[i][2*tx] = s0; st[i][2*tx+1] = s1;
        bf16 o[2] = {__float2bfloat16(s0), __float2bfloat16(s1)};
        *(uint32_t*)&xsb[((size_t)(b * LSEQ + t0 + i)) * EDIM + e0 + 2 * tx] = *(uint32_t*)o;
    }
    __syncthreads();

    for (int i = ty; i < 64; i += 8) {
        xsT[((size_t)b * EDIM + e0 + i) * LSEQ + t0 + tx] = st[tx][i];
        zT [((size_t)b * EDIM + e0 + i) * LSEQ + t0 + tx] = zt[tx][i];
    }
}

// ---------------- chunked parallel selective scan (smem-staged B/C) ----------------
#define CHUNK 64
#define BC_SMEM_BYTES 131072                    // 2048 t * 64 B
#define YSTAGE_BYTES  (8 * (LSEQ + 32) * 2)
#define SCAN_SMEM (BC_SMEM_BYTES + YSTAGE_BYTES)

__device__ __forceinline__ const uint4* bc_addr(const char* bcs, int t, int c) {
    int slot = ((t & 1) * 4 + c) ^ ((t >> 6) & 7);
    return (const uint4*)(bcs + (t >> 1) * 128 + slot * 16);
}

__global__ void __launch_bounds__(256)
scan_kernel(const float* __restrict__ dtT,
            const float* __restrict__ xsT,
            const bf16*  __restrict__ zT,
            const bf16*  __restrict__ bcb,
            const float* __restrict__ A_log,
            const float* __restrict__ D_skip,
            bf16* __restrict__ y) {
    extern __shared__ __align__(16) char dyn[];
    char* bcs = dyn;
    bf16 (*ystage)[LSEQ + 32] = (bf16 (*)[LSEQ + 32])(dyn + BC_SMEM_BYTES);

    const int b    = blockIdx.y;
    const int warp = threadIdx.x >> 5;
    const int lane = threadIdx.x & 31;
    const int e    = blockIdx.x * 8 + warp;

    // ---- stage B/C (bf16, swizzled) ----
    {
        const bf16* src = bcb + (size_t)b * LSEQ * 32;
        for (int k = threadIdx.x; k < 8192; k += 256) {
            int t = k >> 2, c = k & 3;
            int slot = ((t & 1) * 4 + c) ^ ((t >> 6) & 7);
            cp_async16(bcs + (t >> 1) * 128 + slot * 16, src + k * 8);
        }
        cp_commit(); cp_wait<0>();
    }
    __syncthreads();

    float Acoef[NST];
    #pragma unroll
    for (int n = 0; n < NST; n++) Acoef[n] = -__expf(A_log[e * NST + n]);
    const float dsk = D_skip[e];

    const float* dtp = dtT + ((size_t)b * EDIM + e) * LSEQ;
    const float* xsp = xsT + ((size_t)b * EDIM + e) * LSEQ;
    const bf16*  zp  = zT  + ((size_t)b * EDIM + e) * LSEQ;

    const int t0 = lane * CHUNK;

    // ---- pass 1: per-chunk affine summary (P, q) ----
    float P[NST], q[NST];
    #pragma unroll
    for (int n = 0; n < NST; n++) { P[n] = 1.0f; q[n] = 0.0f; }

    for (int s4 = 0; s4 < CHUNK; s4 += 4) {
        float4 d4 = *(const float4*)&dtp[t0 + s4];
        float4 x4 = *(const float4*)&xsp[t0 + s4];
        float dv[4] = {d4.x, d4.y, d4.z, d4.w};
        float xv[4] = {x4.x, x4.y, x4.z, x4.w};
        #pragma unroll
        for (int u = 0; u < 4; u++) {
            const int t = t0 + s4 + u;
            float Bv[NST];
            unpack8(*bc_addr(bcs, t, 0), Bv);
            unpack8(*bc_addr(bcs, t, 1), Bv + 8);
            const float dx = dv[u] * xv[u];
            #pragma unroll
            for (int n = 0; n < NST; n++) {
                float dA = __expf(dv[u] * Acoef[n]);
                q[n] = fmaf(dA, q[n], dx * Bv[n]);
                P[n] *= dA;
            }
        }
    }

    // ---- warp inclusive scan of affine maps over lanes ----
    #pragma unroll
    for (int d = 1; d < 32; d <<= 1) {
        #pragma unroll
        for (int n = 0; n < NST; n++) {
            float Pp = __shfl_up_sync(0xffffffffu, P[n], d);
            float qp = __shfl_up_sync(0xffffffffu, q[n], d);
            if (lane >= d) {
                q[n] = fmaf(P[n], qp, q[n]);
                P[n] *= Pp;
            }
        }
    }
    float h[NST];
    #pragma unroll
    for (int n = 0; n < NST; n++) {
        float v = __shfl_up_sync(0xffffffffu, q[n], 1);
        h[n] = (lane == 0) ? 0.0f : v;
    }

    // ---- pass 2: replay with true h0, produce gated y ----
    for (int s8 = 0; s8 < CHUNK; s8 += 8) {
        float4 d4a = *(const float4*)&dtp[t0 + s8];
        float4 d4b = *(const float4*)&dtp[t0 + s8 + 4];
        float4 x4a = *(const float4*)&xsp[t0 + s8];
        float4 x4b = *(const float4*)&xsp[t0 + s8 + 4];
        uint4  zv8 = *(const uint4*)&zp[t0 + s8];
        float dv[8] = {d4a.x, d4a.y, d4a.z, d4a.w, d4b.x, d4b.y, d4b.z, d4b.w};
        float xv[8] = {x4a.x, x4a.y, x4a.z, x4a.w, x4b.x, x4b.y, x4b.z, x4b.w};
        float zv[8];
        unpack8(zv8, zv);
        #pragma unroll
        for (int u = 0; u < 8; u++) {
            const int t = t0 + s8 + u;
            float Bv[NST], Cv[NST];
            unpack8(*bc_addr(bcs, t, 0), Bv);
            unpack8(*bc_addr(bcs, t, 1), Bv + 8);
            unpack8(*bc_addr(bcs, t, 2), Cv);
            unpack8(*bc_addr(bcs, t, 3), Cv + 8);
            const float dx = dv[u] * xv[u];
            float yacc0 = 0.0f, yacc1 = 0.0f;
            #pragma unroll
            for (int n = 0; n < NST; n += 2) {
                float dA0 = __expf(dv[u] * Acoef[n]);
                float dA1 = __expf(dv[u] * Acoef[n + 1]);
                h[n]     = fmaf(dA0, h[n],     dx * Bv[n]);
                h[n + 1] = fmaf(dA1, h[n + 1], dx * Bv[n + 1]);
                yacc0 = fmaf(h[n],     Cv[n],     yacc0);
                yacc1 = fmaf(h[n + 1], Cv[n + 1], yacc1);
            }
            const float zz  = zv[u];
            const float sig = 1.0f / (1.0f + __expf(-zz));
            const float out = ((yacc0 + yacc1) + xv[u] * dsk) * (zz * sig);
            ystage[warp][t + (t >> 6)] = __float2bfloat16(out);
        }
    }
    __syncthreads();

    const int e0 = blockIdx.x * 8;
    for (int t = threadIdx.x; t < LSEQ; t += 256) {
        bf16 v[8];
        #pragma unroll
        for (int w = 0; w < 8; w++) v[w] = ystage[w][t + (t >> 6)];
        *(uint4*)&y[((size_t)(b * LSEQ + t)) * EDIM + e0] = *(uint4*)v;
    }
}

// ---------------- launcher ----------------
extern "C" void kernel_launch(void* const* d_in, const int* in_sizes, int n_in,
                              void* d_out, int out_size) {
    const float* hidden = (const float*)d_in[0];
    const float* norm_w = (const float*)d_in[1];
    const float* W_in   = (const float*)d_in[2];
    const float* conv_w = (const float*)d_in[3];
    const float* conv_b = (const float*)d_in[4];
    const float* W_x    = (const float*)d_in[5];
    const float* W_dt   = (const float*)d_in[6];
    const float* b_dt   = (const float*)d_in[7];
    const float* A_log  = (const float*)d_in[8];
    const float* D_skip = (const float*)d_in[9];
    const float* W_out  = (const float*)d_in[10];
    float* out = (float*)d_out;

    float *p_dtT, *p_xsT;
    bf16 *p_xzb, *p_zT, *p_nrmb, *p_xsb, *p_dblb, *p_bcb, *p_yb;
    bf16 *p_winb, *p_wxb, *p_wdtb, *p_woutb;
    cudaGetSymbolAddress((void**)&p_xzb,  g_xzb);
    cudaGetSymbolAddress((void**)&p_dtT,  g_dtT);
    cudaGetSymbolAddress((void**)&p_xsT,  g_xsT);
    cudaGetSymbolAddress((void**)&p_zT,   g_zT);
    cudaGetSymbolAddress((void**)&p_nrmb, g_nrmb);
    cudaGetSymbolAddress((void**)&p_xsb,  g_xsb);
    cudaGetSymbolAddress((void**)&p_dblb, g_dblb);
    cudaGetSymbolAddress((void**)&p_bcb,  g_bcb);
    cudaGetSymbolAddress((void**)&p_yb,   g_yb);
    cudaGetSymbolAddress((void**)&p_winb, g_winb);
    cudaGetSymbolAddress((void**)&p_wxb,  g_wxb);
    cudaGetSymbolAddress((void**)&p_wdtb, g_wdtb);
    cudaGetSymbolAddress((void**)&p_woutb, g_woutb);

    // opt-in large dynamic smem for the scan (idempotent; safe pre-capture and under capture)
    cudaFuncSetAttribute(scan_kernel, cudaFuncAttributeMaxDynamicSharedMemorySize, SCAN_SMEM);

    // 0) weight conversion to bf16
    f2bf_kernel<<<(DDIM * 2 * EDIM / 4 + 255) / 256, 256>>>(W_in,  p_winb,  DDIM * 2 * EDIM);
    f2bf_kernel<<<(EDIM * 64 / 4 + 255) / 256, 256>>>(W_x,   p_wxb,   EDIM * 64);
    f2bf_kernel<<<(RRANK * EDIM / 4 + 255) / 256, 256>>>(W_dt, p_wdtb, RRANK * EDIM);
    f2bf_kernel<<<(EDIM * DDIM / 4 + 255) / 256, 256>>>(W_out, p_woutb, EDIM * DDIM);

    // 1) RMSNorm -> bf16
    rmsnorm_kernel<<<NTOK, 128>>>(hidden, norm_w, p_nrmb);

    // 2) xz = nrm @ W_in -> bf16 only
    gemm_bf16<128, 128, 2, 4, 5><<<dim3(2 * EDIM / 128, NTOK / 128), 256>>>(
        p_nrmb, DDIM, p_winb, 2 * EDIM, nullptr, 2 * EDIM,
        NTOK, 2 * EDIM, DDIM, nullptr, p_xzb, nullptr);

    // 3) fused conv + silu + transposes
    conv_fused_kernel<<<dim3(EDIM / 64, LSEQ / 32, BSZ), 256>>>(
        p_xzb, conv_w, conv_b, p_xsb, p_xsT, p_zT);

    // 4) dbl = xs @ W_x -> bf16 full + bf16 compact BC
    gemm_bf16<64, 64, 4, 2, 6><<<dim3(1, NTOK / 64), 256>>>(
        p_xsb, EDIM, p_wxb, 64, nullptr, 64,
        NTOK, 64, EDIM, nullptr, p_dblb, p_bcb);

    // 5) dtT = softplus(dbl[:, :32] @ W_dt + b_dt), transposed write
    dtgemm_kernel<<<dim3(EDIM / 128, NTOK / 128), 256>>>(p_dblb, p_wdtb, b_dt, p_dtT);

    // 6) chunked parallel scan (smem B/C) + gate -> bf16 y
    scan_kernel<<<dim3(EDIM / 8, BSZ), 256, SCAN_SMEM>>>(
        p_dtT, p_xsT, p_zT, p_bcb, A_log, D_skip, p_yb);

    // 7) out = y @ W_out + hidden -> fp32
    gemm_bf16<128, 128, 2, 4, 2><<<dim3(DDIM / 128, NTOK / 128), 256>>>(
        p_yb, EDIM, p_woutb, DDIM, out, DDIM,
        NTOK, DDIM, EDIM, hidden, nullptr, nullptr);
}

// round 8
// speedup vs baseline: 2.0421x; 1.0421x over previous
#include <cuda_runtime.h>
#include <cuda_bf16.h>
#include <cstdint>

using bf16 = __nv_bfloat16;

// Problem constants
#define BSZ 4
#define LSEQ 2048
#define DDIM 512
#define EDIM 1024
#define NST 16
#define RRANK 32
#define NTOK (BSZ * LSEQ)          // 8192

// ---------------- scratch (device globals) ----------------
__device__ bf16  g_xzb[NTOK * 2 * EDIM];    // bf16 xz (conv + z source)
__device__ float g_dtT[NTOK * EDIM];        // [b][e][t] fp32
__device__ float g_xsT[NTOK * EDIM];        // [b][e][t] fp32
__device__ bf16  g_zT [NTOK * EDIM];        // [b][e][t] bf16
__device__ bf16  g_nrmb[NTOK * DDIM];
__device__ bf16  g_xsb [NTOK * EDIM];
__device__ bf16  g_dblb[NTOK * 64];
__device__ bf16  g_bcb [NTOK * 32];
__device__ bf16  g_yb  [NTOK * EDIM];
__device__ bf16  g_winb [DDIM * 2 * EDIM];
__device__ bf16  g_wxb  [EDIM * 64];
__device__ bf16  g_wdtb [RRANK * EDIM];
__device__ bf16  g_woutb[EDIM * DDIM];

// ---------------- PTX helpers ----------------
__device__ __forceinline__ uint32_t smem_u32(const void* p) {
    return (uint32_t)__cvta_generic_to_shared(p);
}
__device__ __forceinline__ void cp_async16(void* s, const void* g) {
    asm volatile("cp.async.cg.shared.global [%0], [%1], 16;\n"
                 :: "r"(smem_u32(s)), "l"(g));
}
__device__ __forceinline__ void cp_commit() { asm volatile("cp.async.commit_group;\n"); }
template <int N> __device__ __forceinline__ void cp_wait() {
    asm volatile("cp.async.wait_group %0;\n" :: "n"(N));
}
__device__ __forceinline__ void ldsm_x4(uint32_t& r0, uint32_t& r1, uint32_t& r2, uint32_t& r3,
                                        uint32_t a) {
    asm volatile("ldmatrix.sync.aligned.m8n8.x4.shared.b16 {%0,%1,%2,%3}, [%4];\n"
                 : "=r"(r0), "=r"(r1), "=r"(r2), "=r"(r3) : "r"(a));
}
__device__ __forceinline__ void ldsm_x4_t(uint32_t& r0, uint32_t& r1, uint32_t& r2, uint32_t& r3,
                                          uint32_t a) {
    asm volatile("ldmatrix.sync.aligned.m8n8.x4.trans.shared.b16 {%0,%1,%2,%3}, [%4];\n"
                 : "=r"(r0), "=r"(r1), "=r"(r2), "=r"(r3) : "r"(a));
}
__device__ __forceinline__ void mma_bf16(float& d0, float& d1, float& d2, float& d3,
                                         uint32_t a0, uint32_t a1, uint32_t a2, uint32_t a3,
                                         uint32_t b0, uint32_t b1) {
    asm volatile("mma.sync.aligned.m16n8k16.row.col.f32.bf16.bf16.f32 "
                 "{%0,%1,%2,%3}, {%4,%5,%6,%7}, {%8,%9}, {%0,%1,%2,%3};\n"
                 : "+f"(d0), "+f"(d1), "+f"(d2), "+f"(d3)
                 : "r"(a0), "r"(a1), "r"(a2), "r"(a3), "r"(b0), "r"(b1));
}
__device__ __forceinline__ float softplus_f(float v) {
    return (v > 20.0f) ? v : log1pf(expf(v));
}
__device__ __forceinline__ void unpack8(uint4 v, float* f) {
    uint32_t u[4] = {v.x, v.y, v.z, v.w};
    #pragma unroll
    for (int j = 0; j < 4; j++) {
        f[2 * j]     = __uint_as_float(u[j] << 16);
        f[2 * j + 1] = __uint_as_float(u[j] & 0xffff0000u);
    }
}
// dA[n] = exp(dtv * Acoef[n]); fast path when Acoef[n] == -(n+1):
// dA[n] = r^(n+1), r = exp(-dtv), via depth-4 multiply tree.
__device__ __forceinline__ void compute_dA(float dtv, const float* Acoef,
                                           bool structured, float* dA) {
    if (structured) {
        const float r1 = __expf(-dtv);
        const float r2 = r1 * r1;
        const float r4 = r2 * r2;
        const float r8 = r4 * r4;
        dA[0] = r1;       dA[1] = r2;       dA[2] = r2 * r1;  dA[3] = r4;
        dA[4] = r4 * r1;  dA[5] = r4 * r2;  dA[6] = r4 * dA[2]; dA[7] = r8;
        dA[8]  = r8 * r1;   dA[9]  = r8 * r2;   dA[10] = r8 * dA[2]; dA[11] = r8 * r4;
        dA[12] = r8 * dA[4]; dA[13] = r8 * dA[5]; dA[14] = r8 * dA[6]; dA[15] = r8 * r8;
    } else {
        #pragma unroll
        for (int n = 0; n < NST; n++) dA[n] = __expf(dtv * Acoef[n]);
    }
}

// ---------------- fp32 -> bf16 convert ----------------
__global__ void f2bf_kernel(const float* __restrict__ in, bf16* __restrict__ out, int n) {
    int i = blockIdx.x * blockDim.x + threadIdx.x;
    if (i * 4 < n) {
        float4 v = *(const float4*)(in + i * 4);
        bf16 o[4] = {__float2bfloat16(v.x), __float2bfloat16(v.y),
                     __float2bfloat16(v.z), __float2bfloat16(v.w)};
        *(uint64_t*)(out + i * 4) = *(uint64_t*)o;
    }
}

// ---------------- RMSNorm -> bf16 ----------------
__global__ void rmsnorm_kernel(const float* __restrict__ x,
                               const float* __restrict__ w,
                               bf16* __restrict__ out) {
    int row = blockIdx.x;
    int tid = threadIdx.x;
    float4 v = ((const float4*)(x + (size_t)row * DDIM))[tid];
    float ss = v.x * v.x + v.y * v.y + v.z * v.z + v.w * v.w;
    #pragma unroll
    for (int o = 16; o > 0; o >>= 1) ss += __shfl_xor_sync(0xffffffffu, ss, o);
    __shared__ float sred[4];
    if ((tid & 31) == 0) sred[tid >> 5] = ss;
    __syncthreads();
    float tot = sred[0] + sred[1] + sred[2] + sred[3];
    float scale = rsqrtf(tot * (1.0f / DDIM) + 1e-6f);
    float4 wv = ((const float4*)w)[tid];
    bf16 o[4] = {__float2bfloat16(v.x * scale * wv.x),
                 __float2bfloat16(v.y * scale * wv.y),
                 __float2bfloat16(v.z * scale * wv.z),
                 __float2bfloat16(v.w * scale * wv.w)};
    *(uint64_t*)(out + (size_t)row * DDIM + tid * 4) = *(uint64_t*)o;
}

// ---------------- bf16 tensor-core GEMM ----------------
// EPI: 2 fp32 + resid | 5 bf16 C2 only | 6 bf16 C2 + compact bf16 C3 (cols>=32)
template <int BM, int BN, int WGM, int WGN, int EPI>
__global__ void __launch_bounds__(WGM * WGN * 32)
gemm_bf16(const bf16* __restrict__ A, int lda,
          const bf16* __restrict__ B, int ldb,
          float* __restrict__ C, int ldc,
          int M, int N, int K,
          const float* __restrict__ resid,
          bf16* __restrict__ C2,
          bf16* __restrict__ C3) {
    constexpr int BK = 32;
    constexpr int NTHR = WGM * WGN * 32;
    constexpr int WM = BM / WGM;
    constexpr int WN = BN / WGN;
    constexpr int MT = WM / 16;
    constexpr int NT = WN / 8;
    static_assert(NT % 2 == 0, "NT even");

    __shared__ __align__(16) bf16 As[2][BM][BK + 8];
    __shared__ __align__(16) bf16 Bs[2][BK][BN + 8];

    const int tid = threadIdx.x;
    const int warp = tid >> 5, lane = tid & 31;
    const int wm = (warp % WGM) * WM;
    const int wn = (warp / WGM) * WN;
    const int rowBase = blockIdx.y * BM;
    const int colBase = blockIdx.x * BN;

    float acc[MT][NT][4];
    #pragma unroll
    for (int i = 0; i < MT; i++)
        #pragma unroll
        for (int j = 0; j < NT; j++)
            #pragma unroll
            for (int q = 0; q < 4; q++) acc[i][j][q] = 0.0f;

    constexpr int A_CHUNKS = BM * BK / 8;
    constexpr int B_CHUNKS = BK * BN / 8;

    auto load_tile = [&](int buf, int k0) {
        #pragma unroll
        for (int c = tid; c < A_CHUNKS; c += NTHR) {
            int row = c / (BK / 8);
            int col = (c % (BK / 8)) * 8;
            cp_async16(&As[buf][row][col],
                       &A[(size_t)(rowBase + row) * lda + k0 + col]);
        }
        #pragma unroll
        for (int c = tid; c < B_CHUNKS; c += NTHR) {
            int row = c / (BN / 8);
            int col = (c % (BN / 8)) * 8;
            cp_async16(&Bs[buf][row][col],
                       &B[(size_t)(k0 + row) * ldb + colBase + col]);
        }
        cp_commit();
    };

    const int KT = K / BK;
    load_tile(0, 0);

    const int arow = lane & 15, acol = (lane >> 4) * 8;
    const int bq = lane >> 3, bl = lane & 7;
    const int bk = (bq & 1) * 8 + bl, bn = (bq >> 1) * 8;

    for (int kt = 0; kt < KT; kt++) {
        const int buf = kt & 1;
        if (kt + 1 < KT) {
            load_tile(buf ^ 1, (kt + 1) * BK);
            cp_wait<1>();
        } else {
            cp_wait<0>();
        }
        __syncthreads();

        #pragma unroll
        for (int ks = 0; ks < 2; ks++) {
            uint32_t a[MT][4];
            #pragma unroll
            for (int mt = 0; mt < MT; mt++)
                ldsm_x4(a[mt][0], a[mt][1], a[mt][2], a[mt][3],
                        smem_u32(&As[buf][wm + mt * 16 + arow][ks * 16 + acol]));
            uint32_t b[NT][2];
            #pragma unroll
            for (int nt2 = 0; nt2 < NT / 2; nt2++) {
                uint32_t r0, r1, r2, r3;
                ldsm_x4_t(r0, r1, r2, r3,
                          smem_u32(&Bs[buf][ks * 16 + bk][wn + nt2 * 16 + bn]));
                b[2 * nt2][0] = r0; b[2 * nt2][1] = r1;
                b[2 * nt2 + 1][0] = r2; b[2 * nt2 + 1][1] = r3;
            }
            #pragma unroll
            for (int mt = 0; mt < MT; mt++)
                #pragma unroll
                for (int nt = 0; nt < NT; nt++)
                    mma_bf16(acc[mt][nt][0], acc[mt][nt][1], acc[mt][nt][2], acc[mt][nt][3],
                             a[mt][0], a[mt][1], a[mt][2], a[mt][3],
                             b[nt][0], b[nt][1]);
        }
        __syncthreads();
    }

    // epilogue
    #pragma unroll
    for (int mt = 0; mt < MT; mt++) {
        #pragma unroll
        for (int nt = 0; nt < NT; nt++) {
            int col = colBase + wn + nt * 8 + (lane & 3) * 2;
            #pragma unroll
            for (int h = 0; h < 2; h++) {
                int row = rowBase + wm + mt * 16 + (lane >> 2) + h * 8;
                float v0 = acc[mt][nt][2 * h + 0];
                float v1 = acc[mt][nt][2 * h + 1];
                if (EPI == 2) {
                    const float2 r = *(const float2*)&resid[(size_t)row * ldc + col];
                    v0 += r.x; v1 += r.y;
                    *(float2*)&C[(size_t)row * ldc + col] = make_float2(v0, v1);
                }
                if (EPI == 5 || EPI == 6) {
                    bf16 o[2] = {__float2bfloat16(v0), __float2bfloat16(v1)};
                    *(uint32_t*)&C2[(size_t)row * ldc + col] = *(uint32_t*)o;
                    if (EPI == 6 && col >= RRANK)
                        *(uint32_t*)&C3[(size_t)row * 32 + col - RRANK] = *(uint32_t*)o;
                }
            }
        }
    }
}

// ---------------- dedicated dt GEMM ----------------
__global__ void __launch_bounds__(256)
dtgemm_kernel(const bf16* __restrict__ A,
              const bf16* __restrict__ B,
              const float* __restrict__ bias,
              float* __restrict__ dtT) {
    __shared__ __align__(16) bf16 As[128][40];
    __shared__ __align__(16) bf16 Bs[32][136];
    __shared__ float sbuf[32][129];

    const int tid = threadIdx.x, warp = tid >> 5, lane = tid & 31;
    const int wm = (warp & 1) * 64;
    const int wn = (warp >> 1) * 32;
    const int rowBase = blockIdx.y * 128;
    const int colBase = blockIdx.x * 128;

    #pragma unroll
    for (int c = tid; c < 512; c += 256) {
        int r = c >> 2, q = (c & 3) * 8;
        cp_async16(&As[r][q], &A[(size_t)(rowBase + r) * 64 + q]);
    }
    #pragma unroll
    for (int c = tid; c < 512; c += 256) {
        int r = c >> 4, q = (c & 15) * 8;
        cp_async16(&Bs[r][q], &B[(size_t)r * EDIM + colBase + q]);
    }
    cp_commit(); cp_wait<0>(); __syncthreads();

    float acc[4][4][4];
    #pragma unroll
    for (int i = 0; i < 4; i++)
        #pragma unroll
        for (int j = 0; j < 4; j++)
            #pragma unroll
            for (int q = 0; q < 4; q++) acc[i][j][q] = 0.0f;

    const int arow = lane & 15, acol = (lane >> 4) * 8;
    const int bq = lane >> 3, bl = lane & 7;
    const int bk = (bq & 1) * 8 + bl, bn = (bq >> 1) * 8;

    #pragma unroll
    for (int ks = 0; ks < 2; ks++) {
        uint32_t a[4][4];
        #pragma unroll
        for (int mt = 0; mt < 4; mt++)
            ldsm_x4(a[mt][0], a[mt][1], a[mt][2], a[mt][3],
                    smem_u32(&As[wm + mt * 16 + arow][ks * 16 + acol]));
        uint32_t b[4][2];
        #pragma unroll
        for (int nt2 = 0; nt2 < 2; nt2++) {
            uint32_t r0, r1, r2, r3;
            ldsm_x4_t(r0, r1, r2, r3,
                      smem_u32(&Bs[ks * 16 + bk][wn + nt2 * 16 + bn]));
            b[2 * nt2][0] = r0; b[2 * nt2][1] = r1;
            b[2 * nt2 + 1][0] = r2; b[2 * nt2 + 1][1] = r3;
        }
        #pragma unroll
        for (int mt = 0; mt < 4; mt++)
            #pragma unroll
            for (int nt = 0; nt < 4; nt++)
                mma_bf16(acc[mt][nt][0], acc[mt][nt][1], acc[mt][nt][2], acc[mt][nt][3],
                         a[mt][0], a[mt][1], a[mt][2], a[mt][3],
                         b[nt][0], b[nt][1]);
    }

    const int bb = rowBase >> 11;
    const int tb = rowBase & 2047;
    #pragma unroll
    for (int cc = 0; cc < 4; cc++) {
        __syncthreads();
        if (wn == cc * 32) {
            #pragma unroll
            for (int mt = 0; mt < 4; mt++)
                #pragma unroll
                for (int nt = 0; nt < 4; nt++) {
                    int c = nt * 8 + (lane & 3) * 2;
                    int col = colBase + wn + c;
                    #pragma unroll
                    for (int h = 0; h < 2; h++) {
                        int r = wm + mt * 16 + (lane >> 2) + h * 8;
                        sbuf[c][r]     = softplus_f(acc[mt][nt][2 * h]     + bias[col]);
                        sbuf[c + 1][r] = softplus_f(acc[mt][nt][2 * h + 1] + bias[col + 1]);
                    }
                }
        }
        __syncthreads();
        for (int j = tid; j < 32 * 128; j += 256) {
            int c = j >> 7, r = j & 127;
            dtT[((size_t)bb * EDIM + colBase + cc * 32 + c) * LSEQ + tb + r] = sbuf[c][r];
        }
    }
}

// ---------------- fused conv+silu+transposes ----------------
__global__ void __launch_bounds__(256)
conv_fused_kernel(const bf16* __restrict__ xzb,
                  const float* __restrict__ conv_w,
                  const float* __restrict__ conv_b,
                  bf16* __restrict__ xsb,
                  float* __restrict__ xsT,
                  bf16* __restrict__ zT) {
    __shared__ float xt[35][65];
    __shared__ float st[32][65];
    __shared__ bf16  zt[32][66];

    const int e0 = blockIdx.x * 64;
    const int t0 = blockIdx.y * 32;
    const int b  = blockIdx.z;
    const int tx = threadIdx.x & 31, ty = threadIdx.x >> 5;

    for (int i = ty; i < 35; i += 8) {
        int t = t0 - 3 + i;
        uint32_t pv = 0;
        if (t >= 0)
            pv = *(const uint32_t*)&xzb[((size_t)(b * LSEQ + t)) * (2 * EDIM) + e0 + 2 * tx];
        bf16 p[2]; *(uint32_t*)p = pv;
        xt[i][2 * tx]     = __bfloat162float(p[0]);
        xt[i][2 * tx + 1] = __bfloat162float(p[1]);
    }
    for (int i = ty; i < 32; i += 8) {
        uint32_t pv = *(const uint32_t*)&xzb[((size_t)(b * LSEQ + t0 + i)) * (2 * EDIM) + EDIM + e0 + 2 * tx];
        *(uint32_t*)&zt[i][2 * tx] = pv;
    }
    __syncthreads();

    const int ea = e0 + 2 * tx, ebx = ea + 1;
    const float w0a = conv_w[ea * 4 + 0], w1a = conv_w[ea * 4 + 1],
                w2a = conv_w[ea * 4 + 2], w3a = conv_w[ea * 4 + 3], bba = conv_b[ea];
    const float w0b = conv_w[ebx * 4 + 0], w1b = conv_w[ebx * 4 + 1],
                w2b = conv_w[ebx * 4 + 2], w3b = conv_w[ebx * 4 + 3], bbb = conv_b[ebx];

    for (int i = ty; i < 32; i += 8) {
        float a0 = bba + w0a * xt[i][2*tx] + w1a * xt[i+1][2*tx]
                       + w2a * xt[i+2][2*tx] + w3a * xt[i+3][2*tx];
        float a1 = bbb + w0b * xt[i][2*tx+1] + w1b * xt[i+1][2*tx+1]
                       + w2b * xt[i+2][2*tx+1] + w3b * xt[i+3][2*tx+1];
        float s0 = a0 / (1.0f + __expf(-a0));
        float s1 = a1 / (1.0f + __expf(-a1));
        st[i][2*tx] = s0; st[i][2*tx+1] = s1;
        bf16 o[2] = {__float2bfloat16(s0), __float2bfloat16(s1)};
        *(uint32_t*)&xsb[((size_t)(b * LSEQ + t0 + i)) * EDIM + e0 + 2 * tx] = *(uint32_t*)o;
    }
    __syncthreads();

    for (int i = ty; i < 64; i += 8) {
        xsT[((size_t)b * EDIM + e0 + i) * LSEQ + t0 + tx] = st[tx][i];
        zT [((size_t)b * EDIM + e0 + i) * LSEQ + t0 + tx] = zt[tx][i];
    }
}

// ---------------- chunked parallel selective scan (smem-staged B/C) ----------------
#define CHUNK 64
#define BC_SMEM_BYTES 131072
#define YSTAGE_BYTES  (8 * (LSEQ + 32) * 2)
#define SCAN_SMEM (BC_SMEM_BYTES + YSTAGE_BYTES)

__device__ __forceinline__ const uint4* bc_addr(const char* bcs, int t, int c) {
    int slot = ((t & 1) * 4 + c) ^ ((t >> 6) & 7);
    return (const uint4*)(bcs + (t >> 1) * 128 + slot * 16);
}

__global__ void __launch_bounds__(256)
scan_kernel(const float* __restrict__ dtT,
            const float* __restrict__ xsT,
            const bf16*  __restrict__ zT,
            const bf16*  __restrict__ bcb,
            const float* __restrict__ A_log,
            const float* __restrict__ D_skip,
            bf16* __restrict__ y) {
    extern __shared__ __align__(16) char dyn[];
    char* bcs = dyn;
    bf16 (*ystage)[LSEQ + 32] = (bf16 (*)[LSEQ + 32])(dyn + BC_SMEM_BYTES);

    const int b    = blockIdx.y;
    const int warp = threadIdx.x >> 5;
    const int lane = threadIdx.x & 31;
    const int e    = blockIdx.x * 8 + warp;

    {
        const bf16* src = bcb + (size_t)b * LSEQ * 32;
        for (int k = threadIdx.x; k < 8192; k += 256) {
            int t = k >> 2, c = k & 3;
            int slot = ((t & 1) * 4 + c) ^ ((t >> 6) & 7);
            cp_async16(bcs + (t >> 1) * 128 + slot * 16, src + k * 8);
        }
        cp_commit(); cp_wait<0>();
    }
    __syncthreads();

    float Acoef[NST];
    bool structured = true;
    #pragma unroll
    for (int n = 0; n < NST; n++) {
        Acoef[n] = -__expf(A_log[e * NST + n]);
        structured &= fabsf(Acoef[n] + (float)(n + 1)) < 1e-4f * (float)(n + 1);
    }
    const float dsk = D_skip[e];

    const float* dtp = dtT + ((size_t)b * EDIM + e) * LSEQ;
    const float* xsp = xsT + ((size_t)b * EDIM + e) * LSEQ;
    const bf16*  zp  = zT  + ((size_t)b * EDIM + e) * LSEQ;

    const int t0 = lane * CHUNK;

    float P[NST], q[NST];
    #pragma unroll
    for (int n = 0; n < NST; n++) { P[n] = 1.0f; q[n] = 0.0f; }

    for (int s4 = 0; s4 < CHUNK; s4 += 4) {
        float4 d4 = *(const float4*)&dtp[t0 + s4];
        float4 x4 = *(const float4*)&xsp[t0 + s4];
        float dv[4] = {d4.x, d4.y, d4.z, d4.w};
        float xv[4] = {x4.x, x4.y, x4.z, x4.w};
        #pragma unroll
        for (int u = 0; u < 4; u++) {
            const int t = t0 + s4 + u;
            float Bv[NST];
            unpack8(*bc_addr(bcs, t, 0), Bv);
            unpack8(*bc_addr(bcs, t, 1), Bv + 8);
            float dA[NST];
            compute_dA(dv[u], Acoef, structured, dA);
            const float dx = dv[u] * xv[u];
            #pragma unroll
            for (int n = 0; n < NST; n++) {
                q[n] = fmaf(dA[n], q[n], dx * Bv[n]);
                P[n] *= dA[n];
            }
        }
    }

    #pragma unroll
    for (int d = 1; d < 32; d <<= 1) {
        #pragma unroll
        for (int n = 0; n < NST; n++) {
            float Pp = __shfl_up_sync(0xffffffffu, P[n], d);
            float qp = __shfl_up_sync(0xffffffffu, q[n], d);
            if (lane >= d) {
                q[n] = fmaf(P[n], qp, q[n]);
                P[n] *= Pp;
            }
        }
    }
    float h[NST];
    #pragma unroll
    for (int n = 0; n < NST; n++) {
        float v = __shfl_up_sync(0xffffffffu, q[n], 1);
        h[n] = (lane == 0) ? 0.0f : v;
    }

    for (int s8 = 0; s8 < CHUNK; s8 += 8) {
        float4 d4a = *(const float4*)&dtp[t0 + s8];
        float4 d4b = *(const float4*)&dtp[t0 + s8 + 4];
        float4 x4a = *(const float4*)&xsp[t0 + s8];
        float4 x4b = *(const float4*)&xsp[t0 + s8 + 4];
        uint4  zv8 = *(const uint4*)&zp[t0 + s8];
        float dv[8] = {d4a.x, d4a.y, d4a.z, d4a.w, d4b.x, d4b.y, d4b.z, d4b.w};
        float xv[8] = {x4a.x, x4a.y, x4a.z, x4a.w, x4b.x, x4b.y, x4b.z, x4b.w};
        float zv[8];
        unpack8(zv8, zv);
        #pragma unroll
        for (int u = 0; u < 8; u++) {
            const int t = t0 + s8 + u;
            float Bv[NST], Cv[NST];
            unpack8(*bc_addr(bcs, t, 0), Bv);
            unpack8(*bc_addr(bcs, t, 1), Bv + 8);
            unpack8(*bc_addr(bcs, t, 2), Cv);
            unpack8(*bc_addr(bcs, t, 3), Cv + 8);
            float dA[NST];
            compute_dA(dv[u], Acoef, structured, dA);
            const float dx = dv[u] * xv[u];
            float yacc0 = 0.0f, yacc1 = 0.0f;
            #pragma unroll
            for (int n = 0; n < NST; n += 2) {
                h[n]     = fmaf(dA[n],     h[n],     dx * Bv[n]);
                h[n + 1] = fmaf(dA[n + 1], h[n + 1], dx * Bv[n + 1]);
                yacc0 = fmaf(h[n],     Cv[n],     yacc0);
                yacc1 = fmaf(h[n + 1], Cv[n + 1], yacc1);
            }
            const float zz  = zv[u];
            const float sig = 1.0f / (1.0f + __expf(-zz));
            const float out = ((yacc0 + yacc1) + xv[u] * dsk) * (zz * sig);
            ystage[warp][t + (t >> 6)] = __float2bfloat16(out);
        }
    }
    __syncthreads();

    const int e0 = blockIdx.x * 8;
    for (int t = threadIdx.x; t < LSEQ; t += 256) {
        bf16 v[8];
        #pragma unroll
        for (int w = 0; w < 8; w++) v[w] = ystage[w][t + (t >> 6)];
        *(uint4*)&y[((size_t)(b * LSEQ + t)) * EDIM + e0] = *(uint4*)v;
    }
}

// ---------------- launcher ----------------
extern "C" void kernel_launch(void* const* d_in, const int* in_sizes, int n_in,
                              void* d_out, int out_size) {
    const float* hidden = (const float*)d_in[0];
    const float* norm_w = (const float*)d_in[1];
    const float* W_in   = (const float*)d_in[2];
    const float* conv_w = (const float*)d_in[3];
    const float* conv_b = (const float*)d_in[4];
    const float* W_x    = (const float*)d_in[5];
    const float* W_dt   = (const float*)d_in[6];
    const float* b_dt   = (const float*)d_in[7];
    const float* A_log  = (const float*)d_in[8];
    const float* D_skip = (const float*)d_in[9];
    const float* W_out  = (const float*)d_in[10];
    float* out = (float*)d_out;

    float *p_dtT, *p_xsT;
    bf16 *p_xzb, *p_zT, *p_nrmb, *p_xsb, *p_dblb, *p_bcb, *p_yb;
    bf16 *p_winb, *p_wxb, *p_wdtb, *p_woutb;
    cudaGetSymbolAddress((void**)&p_xzb,  g_xzb);
    cudaGetSymbolAddress((void**)&p_dtT,  g_dtT);
    cudaGetSymbolAddress((void**)&p_xsT,  g_xsT);
    cudaGetSymbolAddress((void**)&p_zT,   g_zT);
    cudaGetSymbolAddress((void**)&p_nrmb, g_nrmb);
    cudaGetSymbolAddress((void**)&p_xsb,  g_xsb);
    cudaGetSymbolAddress((void**)&p_dblb, g_dblb);
    cudaGetSymbolAddress((void**)&p_bcb,  g_bcb);
    cudaGetSymbolAddress((void**)&p_yb,   g_yb);
    cudaGetSymbolAddress((void**)&p_winb, g_winb);
    cudaGetSymbolAddress((void**)&p_wxb,  g_wxb);
    cudaGetSymbolAddress((void**)&p_wdtb, g_wdtb);
    cudaGetSymbolAddress((void**)&p_woutb, g_woutb);

    cudaFuncSetAttribute(scan_kernel, cudaFuncAttributeMaxDynamicSharedMemorySize, SCAN_SMEM);

    // 0) weight conversion to bf16
    f2bf_kernel<<<(DDIM * 2 * EDIM / 4 + 255) / 256, 256>>>(W_in,  p_winb,  DDIM * 2 * EDIM);
    f2bf_kernel<<<(EDIM * 64 / 4 + 255) / 256, 256>>>(W_x,   p_wxb,   EDIM * 64);
    f2bf_kernel<<<(RRANK * EDIM / 4 + 255) / 256, 256>>>(W_dt, p_wdtb, RRANK * EDIM);
    f2bf_kernel<<<(EDIM * DDIM / 4 + 255) / 256, 256>>>(W_out, p_woutb, EDIM * DDIM);

    // 1) RMSNorm -> bf16
    rmsnorm_kernel<<<NTOK, 128>>>(hidden, norm_w, p_nrmb);

    // 2) xz = nrm @ W_in -> bf16 only
    gemm_bf16<128, 128, 2, 4, 5><<<dim3(2 * EDIM / 128, NTOK / 128), 256>>>(
        p_nrmb, DDIM, p_winb, 2 * EDIM, nullptr, 2 * EDIM,
        NTOK, 2 * EDIM, DDIM, nullptr, p_xzb, nullptr);

    // 3) fused conv + silu + transposes
    conv_fused_kernel<<<dim3(EDIM / 64, LSEQ / 32, BSZ), 256>>>(
        p_xzb, conv_w, conv_b, p_xsb, p_xsT, p_zT);

    // 4) dbl = xs @ W_x -> bf16 full + bf16 compact BC
    gemm_bf16<64, 64, 4, 2, 6><<<dim3(1, NTOK / 64), 256>>>(
        p_xsb, EDIM, p_wxb, 64, nullptr, 64,
        NTOK, 64, EDIM, nullptr, p_dblb, p_bcb);

    // 5) dtT = softplus(dbl[:, :32] @ W_dt + b_dt), transposed write
    dtgemm_kernel<<<dim3(EDIM / 128, NTOK / 128), 256>>>(p_dblb, p_wdtb, b_dt, p_dtT);

    // 6) chunked parallel scan (smem B/C) + gate -> bf16 y
    scan_kernel<<<dim3(EDIM / 8, BSZ), 256, SCAN_SMEM>>>(
        p_dtT, p_xsT, p_zT, p_bcb, A_log, D_skip, p_yb);

    // 7) out = y @ W_out + hidden -> fp32
    gemm_bf16<128, 128, 2, 4, 2><<<dim3(DDIM / 128, NTOK / 128), 256>>>(
        p_yb, EDIM, p_woutb, DDIM, out, DDIM,
        NTOK, DDIM, EDIM, hidden, nullptr, nullptr);
}